// round 4
// baseline (speedup 1.0000x reference)
#include <cuda_runtime.h>
#include <cstdint>

// ============================================================================
// Problem dims
// ============================================================================
#define M_TOTAL 8192      // B*S
#define N_TOTAL 4096      // D_out
#define K_TOTAL 4096      // D_in
#define LORA_RANK 32
#define LORA_SCALE (1.0f / 32.0f)

// GEMM tiling (Ampere-style multistage, tf32 mma.sync m16n8k8)
#define BM 128
#define BN 128
#define BK 32
#define STAGES 3
#define K_ITERS (K_TOTAL / BK)          // 128
#define PAD 36                          // floats per smem row (conflict-free, 16B-aligned)
#define A_ST_FLOATS (BM * PAD)          // 4608
#define B_ST_FLOATS (BN * PAD)          // 4608
#define STAGE_FLOATS (A_ST_FLOATS + B_ST_FLOATS)
#define SMEM_BYTES (STAGES * STAGE_FLOATS * 4)   // 110592

// tf32-rounded operand scratch (device globals: allocation-free scratch)
__device__ float g_Xs[(size_t)M_TOTAL * K_TOTAL];  // [M, K] row-major
__device__ float g_Ws[(size_t)N_TOTAL * K_TOTAL];  // [N, K] row-major (Weff)

// ============================================================================
// Helpers
// ============================================================================
__device__ __forceinline__ uint32_t smem_u32(const void* p) {
    uint32_t a;
    asm("{ .reg .u64 t; cvta.to.shared.u64 t, %1; cvt.u32.u64 %0, t; }" : "=r"(a) : "l"(p));
    return a;
}

__device__ __forceinline__ float tf32_rna(float f) {
    uint32_t r;
    asm("cvt.rna.tf32.f32 %0, %1;" : "=r"(r) : "f"(f));
    return __uint_as_float(r);
}

__device__ __forceinline__ void cp_async16(uint32_t smem_dst, const void* gmem_src) {
    asm volatile("cp.async.cg.shared.global [%0], [%1], 16;" :: "r"(smem_dst), "l"(gmem_src));
}
__device__ __forceinline__ void cp_commit() {
    asm volatile("cp.async.commit_group;" ::: "memory");
}
template <int N>
__device__ __forceinline__ void cp_wait() {
    asm volatile("cp.async.wait_group %0;" :: "n"(N) : "memory");
}

__device__ __forceinline__ void mma_tf32(float& d0, float& d1, float& d2, float& d3,
                                         uint32_t a0, uint32_t a1, uint32_t a2, uint32_t a3,
                                         uint32_t b0, uint32_t b1) {
    asm volatile(
        "mma.sync.aligned.m16n8k8.row.col.f32.tf32.tf32.f32 "
        "{%0,%1,%2,%3}, {%4,%5,%6,%7}, {%8,%9}, {%0,%1,%2,%3};"
        : "+f"(d0), "+f"(d1), "+f"(d2), "+f"(d3)
        : "r"(a0), "r"(a1), "r"(a2), "r"(a3), "r"(b0), "r"(b1));
}

// ============================================================================
// Prep kernels
// ============================================================================

// Round x to tf32 (rna) into g_Xs. One float4 per thread, exact grid.
__global__ __launch_bounds__(256) void round_x_kernel(const float* __restrict__ x) {
    size_t i = (size_t)blockIdx.x * blockDim.x + threadIdx.x;
    float4 v = reinterpret_cast<const float4*>(x)[i];
    v.x = tf32_rna(v.x);
    v.y = tf32_rna(v.y);
    v.z = tf32_rna(v.z);
    v.w = tf32_rna(v.w);
    reinterpret_cast<float4*>(g_Xs)[i] = v;
}

// Weff[o][d] = W[o][d] + SCALE * sum_r A[d][r] * B[r][o], rounded to tf32 (rna).
__global__ __launch_bounds__(256) void weff_kernel(const float* __restrict__ W,
                                                   const float* __restrict__ A,
                                                   const float* __restrict__ B) {
    int o = blockIdx.x;
    __shared__ float bcol[LORA_RANK];
    if (threadIdx.x < LORA_RANK)
        bcol[threadIdx.x] = B[(size_t)threadIdx.x * N_TOTAL + o];
    __syncthreads();

    for (int d = threadIdx.x; d < K_TOTAL; d += 256) {
        const float4* a4 = reinterpret_cast<const float4*>(A + (size_t)d * LORA_RANK);
        float acc = 0.0f;
#pragma unroll
        for (int j = 0; j < LORA_RANK / 4; j++) {
            float4 v = a4[j];
            acc += v.x * bcol[4 * j + 0] + v.y * bcol[4 * j + 1] +
                   v.z * bcol[4 * j + 2] + v.w * bcol[4 * j + 3];
        }
        float w = W[(size_t)o * K_TOTAL + d] + LORA_SCALE * acc;
        g_Ws[(size_t)o * K_TOTAL + d] = tf32_rna(w);
    }
}

// ============================================================================
// Main GEMM: y = Xs @ Ws^T + bias
// 256 threads, 8 warps (warp grid 2M x 4N), warp tile 64x32, m16n8k8 tf32.
// ============================================================================
__global__ __launch_bounds__(256, 2)
void gemm_kernel(const float* __restrict__ Xs, const float* __restrict__ Ws,
                 const float* __restrict__ bias, float* __restrict__ out) {
    extern __shared__ __align__(16) float smem[];

    const int tid = threadIdx.x;
    const int wid = tid >> 5;
    const int lane = tid & 31;
    const int g = lane >> 2;     // group (0..7)
    const int q = lane & 3;      // quad lane (0..3)

    const int warp_m = wid & 1;  // 0..1
    const int warp_n = wid >> 1; // 0..3

    // bid -> (m,n): n fastest (wave covers ~9 A-panels x all B-panels, L2-resident)
    const int n_tiles = N_TOTAL / BN;  // 32
    const int mt = blockIdx.x / n_tiles;
    const int nt = blockIdx.x % n_tiles;
    const int m0 = mt * BM;
    const int n0 = nt * BN;

    const float* Ag = Xs + (size_t)m0 * K_TOTAL;   // A tile base (rows m0.., cols 0..)
    const float* Bg = Ws + (size_t)n0 * K_TOTAL;

    // Per-thread cp.async coordinates: idx = tid + 256*i, row = idx/8, chunk = idx%8
    // (chunk = 16B within the 128B row of the k-slice)
    uint32_t s_base = smem_u32(smem);

    // Accumulators: 4 m-subtiles x 4 n-subtiles x 4 regs
    float d[4][4][4];
#pragma unroll
    for (int i = 0; i < 4; i++)
#pragma unroll
        for (int j = 0; j < 4; j++) {
            d[i][j][0] = 0.f; d[i][j][1] = 0.f; d[i][j][2] = 0.f; d[i][j][3] = 0.f;
        }

    // ---- Stage loader ----
    auto load_stage = [&](int kt, int slot) {
        const float* Asrc = Ag + kt * BK;
        const float* Bsrc = Bg + kt * BK;
        uint32_t sa = s_base + (uint32_t)(slot * STAGE_FLOATS) * 4u;
        uint32_t sbb = sa + A_ST_FLOATS * 4u;
#pragma unroll
        for (int i = 0; i < 4; i++) {
            int idx = tid + 256 * i;          // 0..1023
            int row = idx >> 3;
            int ch = idx & 7;
            cp_async16(sa + (uint32_t)(row * PAD + ch * 4) * 4u,
                       Asrc + (size_t)row * K_TOTAL + ch * 4);
        }
#pragma unroll
        for (int i = 0; i < 4; i++) {
            int idx = tid + 256 * i;
            int row = idx >> 3;
            int ch = idx & 7;
            cp_async16(sbb + (uint32_t)(row * PAD + ch * 4) * 4u,
                       Bsrc + (size_t)row * K_TOTAL + ch * 4);
        }
        cp_commit();
    };

    // Prologue: stages 0..STAGES-2
#pragma unroll
    for (int s = 0; s < STAGES - 1; s++) load_stage(s, s);

    const int Am_base = warp_m * 64;       // warp M offset within tile
    const int Bn_base = warp_n * 32;       // warp N offset

#pragma unroll 1
    for (int kt = 0; kt < K_ITERS; kt++) {
        cp_wait<STAGES - 2>();
        __syncthreads();

        // Refill the slot consumed 1 iteration ago
        if (kt + STAGES - 1 < K_ITERS)
            load_stage(kt + STAGES - 1, (kt + STAGES - 1) % STAGES);

        const float* As = smem + (kt % STAGES) * STAGE_FLOATS;
        const float* Bs = As + A_ST_FLOATS;
        const uint32_t* Au = reinterpret_cast<const uint32_t*>(As);
        const uint32_t* Bu = reinterpret_cast<const uint32_t*>(Bs);

#pragma unroll
        for (int kk = 0; kk < BK; kk += 8) {
            uint32_t a[4][4], b[4][2];
#pragma unroll
            for (int tm = 0; tm < 4; tm++) {
                int r = Am_base + tm * 16 + g;
                a[tm][0] = Au[r * PAD + kk + q];
                a[tm][1] = Au[(r + 8) * PAD + kk + q];
                a[tm][2] = Au[r * PAD + kk + q + 4];
                a[tm][3] = Au[(r + 8) * PAD + kk + q + 4];
            }
#pragma unroll
            for (int tn = 0; tn < 4; tn++) {
                int n = Bn_base + tn * 8 + g;
                b[tn][0] = Bu[n * PAD + kk + q];
                b[tn][1] = Bu[n * PAD + kk + q + 4];
            }
#pragma unroll
            for (int tm = 0; tm < 4; tm++)
#pragma unroll
                for (int tn = 0; tn < 4; tn++)
                    mma_tf32(d[tm][tn][0], d[tm][tn][1], d[tm][tn][2], d[tm][tn][3],
                             a[tm][0], a[tm][1], a[tm][2], a[tm][3],
                             b[tn][0], b[tn][1]);
        }
        __syncthreads();
    }

    // ---- Epilogue: d + bias -> gmem ----
#pragma unroll
    for (int tn = 0; tn < 4; tn++) {
        int col = n0 + Bn_base + tn * 8 + 2 * q;
        float2 bb = *reinterpret_cast<const float2*>(bias + col);
#pragma unroll
        for (int tm = 0; tm < 4; tm++) {
            int row0 = m0 + Am_base + tm * 16 + g;
            float2 v0 = make_float2(d[tm][tn][0] + bb.x, d[tm][tn][1] + bb.y);
            float2 v1 = make_float2(d[tm][tn][2] + bb.x, d[tm][tn][3] + bb.y);
            *reinterpret_cast<float2*>(out + (size_t)row0 * N_TOTAL + col) = v0;
            *reinterpret_cast<float2*>(out + (size_t)(row0 + 8) * N_TOTAL + col) = v1;
        }
    }
}

// ============================================================================
// Host launch
// ============================================================================
extern "C" void kernel_launch(void* const* d_in, const int* in_sizes, int n_in,
                              void* d_out, int out_size) {
    const float* x    = (const float*)d_in[0];  // [4,2048,4096]
    const float* W    = (const float*)d_in[1];  // [4096,4096] (out,in)
    const float* bias = (const float*)d_in[2];  // [4096]
    const float* A    = (const float*)d_in[3];  // [4096,32]
    const float* B    = (const float*)d_in[4];  // [32,4096]
    float* y          = (float*)d_out;          // [4,2048,4096]

    void* xs_ptr = nullptr;
    void* ws_ptr = nullptr;
    cudaGetSymbolAddress(&xs_ptr, g_Xs);
    cudaGetSymbolAddress(&ws_ptr, g_Ws);

    // 1) tf32-round x
    round_x_kernel<<<((size_t)M_TOTAL * K_TOTAL / 4) / 256, 256>>>(x);
    // 2) Weff = W + scale*(A@B)^T, tf32-rounded, stored [N,K]
    weff_kernel<<<N_TOTAL, 256>>>(W, A, B);
    // 3) main GEMM + bias epilogue
    cudaFuncSetAttribute((const void*)gemm_kernel,
                         cudaFuncAttributeMaxDynamicSharedMemorySize, SMEM_BYTES);
    gemm_kernel<<<(M_TOTAL / BM) * (N_TOTAL / BN), 256, SMEM_BYTES>>>(
        (const float*)xs_ptr, (const float*)ws_ptr, bias, y);
}

// round 5
// speedup vs baseline: 1.7312x; 1.7312x over previous
#include <cuda_runtime.h>
#include <cuda_fp16.h>
#include <cstdint>

// ============================================================================
// Problem dims
// ============================================================================
#define M_TOTAL 8192      // B*S
#define N_TOTAL 4096      // D_out
#define K_TOTAL 4096      // D_in
#define LORA_RANK 32
#define LORA_SCALE (1.0f / 32.0f)

// GEMM tiling (fp16 multistage, mma.sync m16n8k16, ldmatrix fragments)
#define BM 128
#define BN 128
#define BK 64                            // halves per stage row (128B)
#define STAGES 3
#define K_ITERS (K_TOTAL / BK)           // 64
#define PAD_H 72                         // halves per smem row (144B, 16B-aligned, +4-bank rotation)
#define A_ST_HALVES (BM * PAD_H)         // 9216
#define B_ST_HALVES (BN * PAD_H)
#define STAGE_HALVES (A_ST_HALVES + B_ST_HALVES)
#define SMEM_BYTES (STAGES * STAGE_HALVES * 2)   // 110592

// fp16 operand scratch (device globals: allocation-free scratch)
__device__ __half g_Xh[(size_t)M_TOTAL * K_TOTAL];  // [M, K] row-major
__device__ __half g_Wh[(size_t)N_TOTAL * K_TOTAL];  // [N, K] row-major (Weff)

// ============================================================================
// Helpers
// ============================================================================
__device__ __forceinline__ uint32_t smem_u32(const void* p) {
    uint32_t a;
    asm("{ .reg .u64 t; cvta.to.shared.u64 t, %1; cvt.u32.u64 %0, t; }" : "=r"(a) : "l"(p));
    return a;
}

__device__ __forceinline__ void cp_async16(uint32_t smem_dst, const void* gmem_src) {
    asm volatile("cp.async.cg.shared.global [%0], [%1], 16;" :: "r"(smem_dst), "l"(gmem_src));
}
__device__ __forceinline__ void cp_commit() {
    asm volatile("cp.async.commit_group;" ::: "memory");
}
template <int N>
__device__ __forceinline__ void cp_wait() {
    asm volatile("cp.async.wait_group %0;" :: "n"(N) : "memory");
}

__device__ __forceinline__ void ldsm_x4(uint32_t& r0, uint32_t& r1, uint32_t& r2, uint32_t& r3,
                                        uint32_t addr) {
    asm volatile("ldmatrix.sync.aligned.m8n8.x4.shared.b16 {%0,%1,%2,%3}, [%4];"
                 : "=r"(r0), "=r"(r1), "=r"(r2), "=r"(r3) : "r"(addr));
}

__device__ __forceinline__ void mma_f16(float& d0, float& d1, float& d2, float& d3,
                                        uint32_t a0, uint32_t a1, uint32_t a2, uint32_t a3,
                                        uint32_t b0, uint32_t b1) {
    asm volatile(
        "mma.sync.aligned.m16n8k16.row.col.f32.f16.f16.f32 "
        "{%0,%1,%2,%3}, {%4,%5,%6,%7}, {%8,%9}, {%0,%1,%2,%3};"
        : "+f"(d0), "+f"(d1), "+f"(d2), "+f"(d3)
        : "r"(a0), "r"(a1), "r"(a2), "r"(a3), "r"(b0), "r"(b1));
}

// ============================================================================
// Prep kernels
// ============================================================================

// Convert x -> fp16 (rn). 8 floats -> 8 halves per thread.
__global__ __launch_bounds__(256) void round_x_h(const float* __restrict__ x) {
    size_t i = (size_t)blockIdx.x * blockDim.x + threadIdx.x;
    float4 v0 = reinterpret_cast<const float4*>(x)[2 * i];
    float4 v1 = reinterpret_cast<const float4*>(x)[2 * i + 1];
    __half2 h[4];
    h[0] = __floats2half2_rn(v0.x, v0.y);
    h[1] = __floats2half2_rn(v0.z, v0.w);
    h[2] = __floats2half2_rn(v1.x, v1.y);
    h[3] = __floats2half2_rn(v1.z, v1.w);
    reinterpret_cast<uint4*>(g_Xh)[i] = *reinterpret_cast<uint4*>(h);
}

// Weff[o][d] = W[o][d] + SCALE * sum_r A[d][r] * B[r][o], converted to fp16 (rn).
__global__ __launch_bounds__(256) void weff_h(const float* __restrict__ W,
                                              const float* __restrict__ A,
                                              const float* __restrict__ B) {
    int o = blockIdx.x;
    __shared__ float bcol[LORA_RANK];
    if (threadIdx.x < LORA_RANK)
        bcol[threadIdx.x] = B[(size_t)threadIdx.x * N_TOTAL + o];
    __syncthreads();

    for (int d = threadIdx.x; d < K_TOTAL; d += 256) {
        const float4* a4 = reinterpret_cast<const float4*>(A + (size_t)d * LORA_RANK);
        float acc = 0.0f;
#pragma unroll
        for (int j = 0; j < LORA_RANK / 4; j++) {
            float4 v = a4[j];
            acc += v.x * bcol[4 * j + 0] + v.y * bcol[4 * j + 1] +
                   v.z * bcol[4 * j + 2] + v.w * bcol[4 * j + 3];
        }
        float w = W[(size_t)o * K_TOTAL + d] + LORA_SCALE * acc;
        g_Wh[(size_t)o * K_TOTAL + d] = __float2half_rn(w);
    }
}

// ============================================================================
// Main GEMM: y = Xh @ Wh^T + bias
// 256 threads, 8 warps (2M x 4N), warp tile 64x32, m16n8k16 fp16, ldmatrix.
// ============================================================================
__global__ __launch_bounds__(256, 2)
void gemm_kernel(const __half* __restrict__ Xh, const __half* __restrict__ Wh,
                 const float* __restrict__ bias, float* __restrict__ out) {
    extern __shared__ __align__(16) __half smem[];

    const int tid = threadIdx.x;
    const int wid = tid >> 5;
    const int lane = tid & 31;
    const int g = lane >> 2;     // group (0..7)
    const int q = lane & 3;      // quad lane (0..3)

    const int warp_m = wid & 1;  // 0..1
    const int warp_n = wid >> 1; // 0..3

    const int n_tiles = N_TOTAL / BN;  // 32
    const int mt = blockIdx.x / n_tiles;
    const int nt = blockIdx.x % n_tiles;
    const int m0 = mt * BM;
    const int n0 = nt * BN;

    const __half* Ag = Xh + (size_t)m0 * K_TOTAL;
    const __half* Bg = Wh + (size_t)n0 * K_TOTAL;

    const uint32_t s_base = smem_u32(smem);

    // Accumulators: 4 m-subtiles x 4 n-subtiles x 4 regs
    float d[4][4][4];
#pragma unroll
    for (int i = 0; i < 4; i++)
#pragma unroll
        for (int j = 0; j < 4; j++) {
            d[i][j][0] = 0.f; d[i][j][1] = 0.f; d[i][j][2] = 0.f; d[i][j][3] = 0.f;
        }

    // ---- Stage loader: 1024 16B chunks each for A and B (row = idx/8, ch = idx%8) ----
    auto load_stage = [&](int kt, int slot) {
        const __half* Asrc = Ag + kt * BK;
        const __half* Bsrc = Bg + kt * BK;
        uint32_t sa = s_base + (uint32_t)(slot * STAGE_HALVES) * 2u;
        uint32_t sbb = sa + A_ST_HALVES * 2u;
#pragma unroll
        for (int i = 0; i < 4; i++) {
            int idx = tid + 256 * i;          // 0..1023
            int row = idx >> 3;
            int ch = idx & 7;
            cp_async16(sa + (uint32_t)(row * PAD_H + ch * 8) * 2u,
                       Asrc + (size_t)row * K_TOTAL + ch * 8);
        }
#pragma unroll
        for (int i = 0; i < 4; i++) {
            int idx = tid + 256 * i;
            int row = idx >> 3;
            int ch = idx & 7;
            cp_async16(sbb + (uint32_t)(row * PAD_H + ch * 8) * 2u,
                       Bsrc + (size_t)row * K_TOTAL + ch * 8);
        }
        cp_commit();
    };

#pragma unroll
    for (int s = 0; s < STAGES - 1; s++) load_stage(s, s);

    const int Am_base = warp_m * 64;
    const int Bn_base = warp_n * 32;

    // ldmatrix per-lane coordinates.
    // A tile order (x4): [rows 0-7,k0-7],[rows 8-15,k0-7],[rows 0-7,k8-15],[rows 8-15,k8-15]
    const int l8 = lane & 7;
    const int aRow = ((lane >> 3) & 1) * 8 + l8;   // + Am_base + tm*16
    const int aK = (lane >> 4) * 8;                // 0 or 8
    // B tile order (x4): [n 0-7,k0-7],[n 0-7,k8-15],[n 8-15,k0-7],[n 8-15,k8-15]
    const int bRow = (lane >> 4) * 8 + l8;         // + Bn_base + tp*16
    const int bK = ((lane >> 3) & 1) * 8;

    uint32_t aOff[4], bOff[2];
#pragma unroll
    for (int tm = 0; tm < 4; tm++)
        aOff[tm] = (uint32_t)(((Am_base + tm * 16 + aRow) * PAD_H + aK) * 2);
#pragma unroll
    for (int tp = 0; tp < 2; tp++)
        bOff[tp] = (uint32_t)(((Bn_base + tp * 16 + bRow) * PAD_H + bK) * 2 +
                              A_ST_HALVES * 2);

#pragma unroll 1
    for (int kt = 0; kt < K_ITERS; kt++) {
        cp_wait<STAGES - 2>();
        __syncthreads();

        if (kt + STAGES - 1 < K_ITERS)
            load_stage(kt + STAGES - 1, (kt + STAGES - 1) % STAGES);

        const uint32_t st = s_base + (uint32_t)((kt % STAGES) * STAGE_HALVES) * 2u;

#pragma unroll
        for (int kk = 0; kk < BK; kk += 16) {
            uint32_t a[4][4], b[2][4];
#pragma unroll
            for (int tm = 0; tm < 4; tm++)
                ldsm_x4(a[tm][0], a[tm][1], a[tm][2], a[tm][3], st + aOff[tm] + kk * 2);
#pragma unroll
            for (int tp = 0; tp < 2; tp++)
                ldsm_x4(b[tp][0], b[tp][1], b[tp][2], b[tp][3], st + bOff[tp] + kk * 2);
#pragma unroll
            for (int tm = 0; tm < 4; tm++)
#pragma unroll
                for (int tn = 0; tn < 4; tn++)
                    mma_f16(d[tm][tn][0], d[tm][tn][1], d[tm][tn][2], d[tm][tn][3],
                            a[tm][0], a[tm][1], a[tm][2], a[tm][3],
                            b[tn >> 1][2 * (tn & 1)], b[tn >> 1][2 * (tn & 1) + 1]);
        }
        __syncthreads();
    }

    // ---- Epilogue: d + bias -> gmem ----
#pragma unroll
    for (int tn = 0; tn < 4; tn++) {
        int col = n0 + Bn_base + tn * 8 + 2 * q;
        float2 bb = *reinterpret_cast<const float2*>(bias + col);
#pragma unroll
        for (int tm = 0; tm < 4; tm++) {
            int row0 = m0 + Am_base + tm * 16 + g;
            float2 v0 = make_float2(d[tm][tn][0] + bb.x, d[tm][tn][1] + bb.y);
            float2 v1 = make_float2(d[tm][tn][2] + bb.x, d[tm][tn][3] + bb.y);
            *reinterpret_cast<float2*>(out + (size_t)row0 * N_TOTAL + col) = v0;
            *reinterpret_cast<float2*>(out + (size_t)(row0 + 8) * N_TOTAL + col) = v1;
        }
    }
}

// ============================================================================
// Host launch
// ============================================================================
extern "C" void kernel_launch(void* const* d_in, const int* in_sizes, int n_in,
                              void* d_out, int out_size) {
    const float* x    = (const float*)d_in[0];  // [4,2048,4096]
    const float* W    = (const float*)d_in[1];  // [4096,4096] (out,in)
    const float* bias = (const float*)d_in[2];  // [4096]
    const float* A    = (const float*)d_in[3];  // [4096,32]
    const float* B    = (const float*)d_in[4];  // [32,4096]
    float* y          = (float*)d_out;          // [4,2048,4096]

    void* xh_ptr = nullptr;
    void* wh_ptr = nullptr;
    cudaGetSymbolAddress(&xh_ptr, g_Xh);
    cudaGetSymbolAddress(&wh_ptr, g_Wh);

    // 1) x -> fp16
    round_x_h<<<((size_t)M_TOTAL * K_TOTAL / 8) / 256, 256>>>(x);
    // 2) Weff = W + scale*(A@B)^T -> fp16, stored [N,K]
    weff_h<<<N_TOTAL, 256>>>(W, A, B);
    // 3) main GEMM + bias epilogue
    cudaFuncSetAttribute((const void*)gemm_kernel,
                         cudaFuncAttributeMaxDynamicSharedMemorySize, SMEM_BYTES);
    gemm_kernel<<<(M_TOTAL / BM) * (N_TOTAL / BN), 256, SMEM_BYTES>>>(
        (const __half*)xh_ptr, (const __half*)wh_ptr, bias, y);
}

// round 6
// speedup vs baseline: 2.3086x; 1.3336x over previous
#include <cuda_runtime.h>
#include <cuda_fp16.h>
#include <cstdint>

// ============================================================================
// Problem dims
// ============================================================================
#define M_TOTAL 8192      // B*S
#define N_TOTAL 4096      // D_out
#define K_TOTAL 4096      // D_in
#define LORA_RANK 32
#define LORA_SCALE (1.0f / 32.0f)

// GEMM tiling (fp16 multistage, mma.sync m16n8k16, ldmatrix fragments)
#define BM 128
#define BN 128
#define BK 64                            // halves per stage row (128B)
#define STAGES 3
#define K_ITERS (K_TOTAL / BK)           // 64
#define PAD_H 72                         // halves per smem row (144B, 16B-aligned, +4-bank rotation)
#define A_ST_HALVES (BM * PAD_H)         // 9216
#define B_ST_HALVES (BN * PAD_H)
#define STAGE_HALVES (A_ST_HALVES + B_ST_HALVES)
#define SMEM_BYTES (STAGES * STAGE_HALVES * 2)   // 110592

// fp16 operand scratch (device globals: allocation-free scratch)
__device__ __half g_Xh[(size_t)M_TOTAL * K_TOTAL];  // [M, K] row-major
__device__ __half g_Wh[(size_t)N_TOTAL * K_TOTAL];  // [N, K] row-major (Weff)

// ============================================================================
// Helpers
// ============================================================================
__device__ __forceinline__ uint32_t smem_u32(const void* p) {
    uint32_t a;
    asm("{ .reg .u64 t; cvta.to.shared.u64 t, %1; cvt.u32.u64 %0, t; }" : "=r"(a) : "l"(p));
    return a;
}

__device__ __forceinline__ void cp_async16(uint32_t smem_dst, const void* gmem_src) {
    asm volatile("cp.async.cg.shared.global [%0], [%1], 16;" :: "r"(smem_dst), "l"(gmem_src));
}
__device__ __forceinline__ void cp_commit() {
    asm volatile("cp.async.commit_group;" ::: "memory");
}
template <int N>
__device__ __forceinline__ void cp_wait() {
    asm volatile("cp.async.wait_group %0;" :: "n"(N) : "memory");
}

__device__ __forceinline__ void ldsm_x4(uint32_t& r0, uint32_t& r1, uint32_t& r2, uint32_t& r3,
                                        uint32_t addr) {
    asm volatile("ldmatrix.sync.aligned.m8n8.x4.shared.b16 {%0,%1,%2,%3}, [%4];"
                 : "=r"(r0), "=r"(r1), "=r"(r2), "=r"(r3) : "r"(addr));
}

__device__ __forceinline__ void mma_f16(float& d0, float& d1, float& d2, float& d3,
                                        uint32_t a0, uint32_t a1, uint32_t a2, uint32_t a3,
                                        uint32_t b0, uint32_t b1) {
    asm volatile(
        "mma.sync.aligned.m16n8k16.row.col.f32.f16.f16.f32 "
        "{%0,%1,%2,%3}, {%4,%5,%6,%7}, {%8,%9}, {%0,%1,%2,%3};"
        : "+f"(d0), "+f"(d1), "+f"(d2), "+f"(d3)
        : "r"(a0), "r"(a1), "r"(a2), "r"(a3), "r"(b0), "r"(b1));
}

// ============================================================================
// Prep kernels
// ============================================================================

// Convert x -> fp16 (rn). 8 floats -> 8 halves per thread.
__global__ __launch_bounds__(256) void round_x_h(const float* __restrict__ x) {
    size_t i = (size_t)blockIdx.x * blockDim.x + threadIdx.x;
    float4 v0 = reinterpret_cast<const float4*>(x)[2 * i];
    float4 v1 = reinterpret_cast<const float4*>(x)[2 * i + 1];
    __half2 h[4];
    h[0] = __floats2half2_rn(v0.x, v0.y);
    h[1] = __floats2half2_rn(v0.z, v0.w);
    h[2] = __floats2half2_rn(v1.x, v1.y);
    h[3] = __floats2half2_rn(v1.z, v1.w);
    reinterpret_cast<uint4*>(g_Xh)[i] = *reinterpret_cast<uint4*>(h);
}

// Weff[o][d] = W[o][d] + SCALE * sum_r A[d][r] * B[r][o], fp16 (rn).
// o-tiled: block owns 32 o-columns; A row lives in registers and feeds all 32
// outputs -> A is read ONCE total (64MB L2) instead of once per o (2GB).
#define O_TILE 32
__global__ __launch_bounds__(256) void weff_h(const float* __restrict__ W,
                                              const float* __restrict__ A,
                                              const float* __restrict__ B) {
    __shared__ float Bs[O_TILE][LORA_RANK];   // [o_local][r] (transposed B tile)
    const int o0 = blockIdx.x * O_TILE;

    for (int idx = threadIdx.x; idx < O_TILE * LORA_RANK; idx += 256) {
        int r = idx >> 5;
        int o = idx & 31;
        Bs[o][r] = B[(size_t)r * N_TOTAL + o0 + o];   // coalesced over o
    }
    __syncthreads();

#pragma unroll 1
    for (int it = 0; it < K_TOTAL / 256; it++) {
        const int d = it * 256 + threadIdx.x;
        float4 a4[LORA_RANK / 4];
        const float4* arow = reinterpret_cast<const float4*>(A + (size_t)d * LORA_RANK);
#pragma unroll
        for (int j = 0; j < LORA_RANK / 4; j++) a4[j] = arow[j];

#pragma unroll 4
        for (int o = 0; o < O_TILE; o++) {
            const float4* b4 = reinterpret_cast<const float4*>(Bs[o]);  // warp-broadcast
            float acc = 0.0f;
#pragma unroll
            for (int j = 0; j < LORA_RANK / 4; j++) {
                float4 b = b4[j];
                acc += a4[j].x * b.x + a4[j].y * b.y + a4[j].z * b.z + a4[j].w * b.w;
            }
            const size_t oi = (size_t)(o0 + o) * K_TOTAL + d;   // lanes: consecutive d -> coalesced
            g_Wh[oi] = __float2half_rn(W[oi] + LORA_SCALE * acc);
        }
    }
}

// ============================================================================
// Main GEMM: y = Xh @ Wh^T + bias
// 256 threads, 8 warps (2M x 4N), warp tile 64x32, m16n8k16 fp16, ldmatrix.
// ============================================================================
__global__ __launch_bounds__(256, 2)
void gemm_kernel(const __half* __restrict__ Xh, const __half* __restrict__ Wh,
                 const float* __restrict__ bias, float* __restrict__ out) {
    extern __shared__ __align__(16) __half smem[];

    const int tid = threadIdx.x;
    const int wid = tid >> 5;
    const int lane = tid & 31;
    const int g = lane >> 2;     // group (0..7)
    const int q = lane & 3;      // quad lane (0..3)

    const int warp_m = wid & 1;  // 0..1
    const int warp_n = wid >> 1; // 0..3

    const int n_tiles = N_TOTAL / BN;  // 32
    const int mt = blockIdx.x / n_tiles;
    const int nt = blockIdx.x % n_tiles;
    const int m0 = mt * BM;
    const int n0 = nt * BN;

    const __half* Ag = Xh + (size_t)m0 * K_TOTAL;
    const __half* Bg = Wh + (size_t)n0 * K_TOTAL;

    const uint32_t s_base = smem_u32(smem);

    // Accumulators: 4 m-subtiles x 4 n-subtiles x 4 regs
    float d[4][4][4];
#pragma unroll
    for (int i = 0; i < 4; i++)
#pragma unroll
        for (int j = 0; j < 4; j++) {
            d[i][j][0] = 0.f; d[i][j][1] = 0.f; d[i][j][2] = 0.f; d[i][j][3] = 0.f;
        }

    // ---- Stage loader: 1024 16B chunks each for A and B (row = idx/8, ch = idx%8) ----
    auto load_stage = [&](int kt, int slot) {
        const __half* Asrc = Ag + kt * BK;
        const __half* Bsrc = Bg + kt * BK;
        uint32_t sa = s_base + (uint32_t)(slot * STAGE_HALVES) * 2u;
        uint32_t sbb = sa + A_ST_HALVES * 2u;
#pragma unroll
        for (int i = 0; i < 4; i++) {
            int idx = tid + 256 * i;          // 0..1023
            int row = idx >> 3;
            int ch = idx & 7;
            cp_async16(sa + (uint32_t)(row * PAD_H + ch * 8) * 2u,
                       Asrc + (size_t)row * K_TOTAL + ch * 8);
        }
#pragma unroll
        for (int i = 0; i < 4; i++) {
            int idx = tid + 256 * i;
            int row = idx >> 3;
            int ch = idx & 7;
            cp_async16(sbb + (uint32_t)(row * PAD_H + ch * 8) * 2u,
                       Bsrc + (size_t)row * K_TOTAL + ch * 8);
        }
        cp_commit();
    };

#pragma unroll
    for (int s = 0; s < STAGES - 1; s++) load_stage(s, s);

    const int Am_base = warp_m * 64;
    const int Bn_base = warp_n * 32;

    // ldmatrix per-lane coordinates.
    const int l8 = lane & 7;
    const int aRow = ((lane >> 3) & 1) * 8 + l8;   // + Am_base + tm*16
    const int aK = (lane >> 4) * 8;                // 0 or 8
    const int bRow = (lane >> 4) * 8 + l8;         // + Bn_base + tp*16
    const int bK = ((lane >> 3) & 1) * 8;

    uint32_t aOff[4], bOff[2];
#pragma unroll
    for (int tm = 0; tm < 4; tm++)
        aOff[tm] = (uint32_t)(((Am_base + tm * 16 + aRow) * PAD_H + aK) * 2);
#pragma unroll
    for (int tp = 0; tp < 2; tp++)
        bOff[tp] = (uint32_t)(((Bn_base + tp * 16 + bRow) * PAD_H + bK) * 2 +
                              A_ST_HALVES * 2);

#pragma unroll 1
    for (int kt = 0; kt < K_ITERS; kt++) {
        cp_wait<STAGES - 2>();
        // Single barrier per iteration: after it, (a) stage kt data is visible to
        // all warps, and (b) all warps have finished reading the slot that the
        // load below overwrites ((kt+2)%3 == slot read in iteration kt-1).
        __syncthreads();

        if (kt + STAGES - 1 < K_ITERS)
            load_stage(kt + STAGES - 1, (kt + STAGES - 1) % STAGES);

        const uint32_t st = s_base + (uint32_t)((kt % STAGES) * STAGE_HALVES) * 2u;

#pragma unroll
        for (int kk = 0; kk < BK; kk += 16) {
            uint32_t a[4][4], b[2][4];
#pragma unroll
            for (int tm = 0; tm < 4; tm++)
                ldsm_x4(a[tm][0], a[tm][1], a[tm][2], a[tm][3], st + aOff[tm] + kk * 2);
#pragma unroll
            for (int tp = 0; tp < 2; tp++)
                ldsm_x4(b[tp][0], b[tp][1], b[tp][2], b[tp][3], st + bOff[tp] + kk * 2);
#pragma unroll
            for (int tm = 0; tm < 4; tm++)
#pragma unroll
                for (int tn = 0; tn < 4; tn++)
                    mma_f16(d[tm][tn][0], d[tm][tn][1], d[tm][tn][2], d[tm][tn][3],
                            a[tm][0], a[tm][1], a[tm][2], a[tm][3],
                            b[tn >> 1][2 * (tn & 1)], b[tn >> 1][2 * (tn & 1) + 1]);
        }
    }

    // ---- Epilogue: d + bias -> gmem ----
#pragma unroll
    for (int tn = 0; tn < 4; tn++) {
        int col = n0 + Bn_base + tn * 8 + 2 * q;
        float2 bb = *reinterpret_cast<const float2*>(bias + col);
#pragma unroll
        for (int tm = 0; tm < 4; tm++) {
            int row0 = m0 + Am_base + tm * 16 + g;
            float2 v0 = make_float2(d[tm][tn][0] + bb.x, d[tm][tn][1] + bb.y);
            float2 v1 = make_float2(d[tm][tn][2] + bb.x, d[tm][tn][3] + bb.y);
            *reinterpret_cast<float2*>(out + (size_t)row0 * N_TOTAL + col) = v0;
            *reinterpret_cast<float2*>(out + (size_t)(row0 + 8) * N_TOTAL + col) = v1;
        }
    }
}

// ============================================================================
// Host launch
// ============================================================================
extern "C" void kernel_launch(void* const* d_in, const int* in_sizes, int n_in,
                              void* d_out, int out_size) {
    const float* x    = (const float*)d_in[0];  // [4,2048,4096]
    const float* W    = (const float*)d_in[1];  // [4096,4096] (out,in)
    const float* bias = (const float*)d_in[2];  // [4096]
    const float* A    = (const float*)d_in[3];  // [4096,32]
    const float* B    = (const float*)d_in[4];  // [32,4096]
    float* y          = (float*)d_out;          // [4,2048,4096]

    void* xh_ptr = nullptr;
    void* wh_ptr = nullptr;
    cudaGetSymbolAddress(&xh_ptr, g_Xh);
    cudaGetSymbolAddress(&wh_ptr, g_Wh);

    // 1) x -> fp16
    round_x_h<<<((size_t)M_TOTAL * K_TOTAL / 8) / 256, 256>>>(x);
    // 2) Weff = W + scale*(A@B)^T -> fp16, stored [N,K] (o-tiled, FMA-bound)
    weff_h<<<N_TOTAL / O_TILE, 256>>>(W, A, B);
    // 3) main GEMM + bias epilogue
    cudaFuncSetAttribute((const void*)gemm_kernel,
                         cudaFuncAttributeMaxDynamicSharedMemorySize, SMEM_BYTES);
    gemm_kernel<<<(M_TOTAL / BM) * (N_TOTAL / BN), 256, SMEM_BYTES>>>(
        (const __half*)xh_ptr, (const __half*)wh_ptr, bias, y);
}

// round 7
// speedup vs baseline: 2.4384x; 1.0563x over previous
#include <cuda_runtime.h>
#include <cuda_fp16.h>
#include <cstdint>

// ============================================================================
// Problem dims
// ============================================================================
#define M_TOTAL 8192      // B*S
#define N_TOTAL 4096      // D_out
#define K_TOTAL 4096      // D_in
#define LORA_RANK 32
#define LORA_SCALE (1.0f / 32.0f)

// GEMM tiling (fp16 multistage, mma.sync m16n8k16, ldmatrix fragments)
#define BM 128
#define BN 128
#define BK 64                            // halves per stage row (128B)
#define STAGES 3
#define K_ITERS (K_TOTAL / BK)           // 64
#define PAD_H 72                         // halves per smem row (144B, 16B-aligned, +4-bank rotation)
#define A_ST_HALVES (BM * PAD_H)         // 9216
#define B_ST_HALVES (BN * PAD_H)
#define STAGE_HALVES (A_ST_HALVES + B_ST_HALVES)
#define SMEM_BYTES (STAGES * STAGE_HALVES * 2)   // 110592

// Fused prep grid split
#define O_TILE 32
#define WEFF_BLOCKS (N_TOTAL / O_TILE)                        // 128 (scheduled first)
#define CONV_BLOCKS ((M_TOTAL * K_TOTAL / 8) / 256)           // 16384

// fp16 operand scratch (device globals: allocation-free scratch)
__device__ __half g_Xh[(size_t)M_TOTAL * K_TOTAL];  // [M, K] row-major
__device__ __half g_Wh[(size_t)N_TOTAL * K_TOTAL];  // [N, K] row-major (Weff)

// ============================================================================
// Helpers
// ============================================================================
__device__ __forceinline__ uint32_t smem_u32(const void* p) {
    uint32_t a;
    asm("{ .reg .u64 t; cvta.to.shared.u64 t, %1; cvt.u32.u64 %0, t; }" : "=r"(a) : "l"(p));
    return a;
}

__device__ __forceinline__ void cp_async16(uint32_t smem_dst, const void* gmem_src) {
    asm volatile("cp.async.cg.shared.global [%0], [%1], 16;" :: "r"(smem_dst), "l"(gmem_src));
}
__device__ __forceinline__ void cp_commit() {
    asm volatile("cp.async.commit_group;" ::: "memory");
}
template <int N>
__device__ __forceinline__ void cp_wait() {
    asm volatile("cp.async.wait_group %0;" :: "n"(N) : "memory");
}

__device__ __forceinline__ void ldsm_x4(uint32_t& r0, uint32_t& r1, uint32_t& r2, uint32_t& r3,
                                        uint32_t addr) {
    asm volatile("ldmatrix.sync.aligned.m8n8.x4.shared.b16 {%0,%1,%2,%3}, [%4];"
                 : "=r"(r0), "=r"(r1), "=r"(r2), "=r"(r3) : "r"(addr));
}

__device__ __forceinline__ void mma_f16(float& d0, float& d1, float& d2, float& d3,
                                        uint32_t a0, uint32_t a1, uint32_t a2, uint32_t a3,
                                        uint32_t b0, uint32_t b1) {
    asm volatile(
        "mma.sync.aligned.m16n8k16.row.col.f32.f16.f16.f32 "
        "{%0,%1,%2,%3}, {%4,%5,%6,%7}, {%8,%9}, {%0,%1,%2,%3};"
        : "+f"(d0), "+f"(d1), "+f"(d2), "+f"(d3)
        : "r"(a0), "r"(a1), "r"(a2), "r"(a3), "r"(b0), "r"(b1));
}

// ============================================================================
// Fused prep kernel: blocks [0, WEFF_BLOCKS) build Weff (FMA/L2-bound),
// blocks [WEFF_BLOCKS, WEFF_BLOCKS+CONV_BLOCKS) convert x -> fp16 (DRAM-bound).
// weff blocks are scheduled first so both phases overlap on disjoint resources.
// ============================================================================
__global__ __launch_bounds__(256) void prep_kernel(const float* __restrict__ x,
                                                   const float* __restrict__ W,
                                                   const float* __restrict__ A,
                                                   const float* __restrict__ B) {
    __shared__ float Bs[O_TILE][LORA_RANK];   // used by weff branch only (4KB)

    if (blockIdx.x < WEFF_BLOCKS) {
        // ---- Weff[o][d] = W[o][d] + SCALE * sum_r A[d][r]*B[r][o] -> fp16 ----
        const int o0 = blockIdx.x * O_TILE;

        for (int idx = threadIdx.x; idx < O_TILE * LORA_RANK; idx += 256) {
            int r = idx >> 5;
            int o = idx & 31;
            Bs[o][r] = B[(size_t)r * N_TOTAL + o0 + o];   // coalesced over o
        }
        __syncthreads();

#pragma unroll 1
        for (int it = 0; it < K_TOTAL / 256; it++) {
            const int d = it * 256 + threadIdx.x;
            float4 a4[LORA_RANK / 4];
            const float4* arow = reinterpret_cast<const float4*>(A + (size_t)d * LORA_RANK);
#pragma unroll
            for (int j = 0; j < LORA_RANK / 4; j++) a4[j] = arow[j];

#pragma unroll 4
            for (int o = 0; o < O_TILE; o++) {
                const float4* b4 = reinterpret_cast<const float4*>(Bs[o]);  // warp-broadcast
                float acc = 0.0f;
#pragma unroll
                for (int j = 0; j < LORA_RANK / 4; j++) {
                    float4 b = b4[j];
                    acc += a4[j].x * b.x + a4[j].y * b.y + a4[j].z * b.z + a4[j].w * b.w;
                }
                const size_t oi = (size_t)(o0 + o) * K_TOTAL + d;   // coalesced over d
                g_Wh[oi] = __float2half_rn(W[oi] + LORA_SCALE * acc);
            }
        }
    } else {
        // ---- x -> fp16 (rn): 8 floats per thread ----
        size_t i = (size_t)(blockIdx.x - WEFF_BLOCKS) * 256 + threadIdx.x;
        float4 v0 = reinterpret_cast<const float4*>(x)[2 * i];
        float4 v1 = reinterpret_cast<const float4*>(x)[2 * i + 1];
        __half2 h[4];
        h[0] = __floats2half2_rn(v0.x, v0.y);
        h[1] = __floats2half2_rn(v0.z, v0.w);
        h[2] = __floats2half2_rn(v1.x, v1.y);
        h[3] = __floats2half2_rn(v1.z, v1.w);
        reinterpret_cast<uint4*>(g_Xh)[i] = *reinterpret_cast<uint4*>(h);
    }
}

// ============================================================================
// Main GEMM: y = Xh @ Wh^T + bias
// 256 threads, 8 warps (2M x 4N), warp tile 64x32, m16n8k16 fp16, ldmatrix.
// ============================================================================
__global__ __launch_bounds__(256, 2)
void gemm_kernel(const __half* __restrict__ Xh, const __half* __restrict__ Wh,
                 const float* __restrict__ bias, float* __restrict__ out) {
    extern __shared__ __align__(16) __half smem[];

    const int tid = threadIdx.x;
    const int wid = tid >> 5;
    const int lane = tid & 31;
    const int g = lane >> 2;     // group (0..7)
    const int q = lane & 3;      // quad lane (0..3)

    const int warp_m = wid & 1;  // 0..1
    const int warp_n = wid >> 1; // 0..3

    const int n_tiles = N_TOTAL / BN;  // 32
    const int mt = blockIdx.x / n_tiles;
    const int nt = blockIdx.x % n_tiles;
    const int m0 = mt * BM;
    const int n0 = nt * BN;

    const __half* Ag = Xh + (size_t)m0 * K_TOTAL;
    const __half* Bg = Wh + (size_t)n0 * K_TOTAL;

    const uint32_t s_base = smem_u32(smem);

    // Accumulators: 4 m-subtiles x 4 n-subtiles x 4 regs
    float d[4][4][4];
#pragma unroll
    for (int i = 0; i < 4; i++)
#pragma unroll
        for (int j = 0; j < 4; j++) {
            d[i][j][0] = 0.f; d[i][j][1] = 0.f; d[i][j][2] = 0.f; d[i][j][3] = 0.f;
        }

    // ---- Stage loader: 1024 16B chunks each for A and B (row = idx/8, ch = idx%8) ----
    auto load_stage = [&](int kt, int slot) {
        const __half* Asrc = Ag + kt * BK;
        const __half* Bsrc = Bg + kt * BK;
        uint32_t sa = s_base + (uint32_t)(slot * STAGE_HALVES) * 2u;
        uint32_t sbb = sa + A_ST_HALVES * 2u;
#pragma unroll
        for (int i = 0; i < 4; i++) {
            int idx = tid + 256 * i;          // 0..1023
            int row = idx >> 3;
            int ch = idx & 7;
            cp_async16(sa + (uint32_t)(row * PAD_H + ch * 8) * 2u,
                       Asrc + (size_t)row * K_TOTAL + ch * 8);
        }
#pragma unroll
        for (int i = 0; i < 4; i++) {
            int idx = tid + 256 * i;
            int row = idx >> 3;
            int ch = idx & 7;
            cp_async16(sbb + (uint32_t)(row * PAD_H + ch * 8) * 2u,
                       Bsrc + (size_t)row * K_TOTAL + ch * 8);
        }
        cp_commit();
    };

#pragma unroll
    for (int s = 0; s < STAGES - 1; s++) load_stage(s, s);

    const int Am_base = warp_m * 64;
    const int Bn_base = warp_n * 32;

    // ldmatrix per-lane coordinates.
    const int l8 = lane & 7;
    const int aRow = ((lane >> 3) & 1) * 8 + l8;   // + Am_base + tm*16
    const int aK = (lane >> 4) * 8;                // 0 or 8
    const int bRow = (lane >> 4) * 8 + l8;         // + Bn_base + tp*16
    const int bK = ((lane >> 3) & 1) * 8;

    uint32_t aOff[4], bOff[2];
#pragma unroll
    for (int tm = 0; tm < 4; tm++)
        aOff[tm] = (uint32_t)(((Am_base + tm * 16 + aRow) * PAD_H + aK) * 2);
#pragma unroll
    for (int tp = 0; tp < 2; tp++)
        bOff[tp] = (uint32_t)(((Bn_base + tp * 16 + bRow) * PAD_H + bK) * 2 +
                              A_ST_HALVES * 2);

#pragma unroll 1
    for (int kt = 0; kt < K_ITERS; kt++) {
        cp_wait<STAGES - 2>();
        // Single barrier per iteration: after it, (a) stage kt data is visible to
        // all warps, and (b) all warps have finished reading the slot that the
        // load below overwrites ((kt+2)%3 == slot read in iteration kt-1).
        __syncthreads();

        if (kt + STAGES - 1 < K_ITERS)
            load_stage(kt + STAGES - 1, (kt + STAGES - 1) % STAGES);

        const uint32_t st = s_base + (uint32_t)((kt % STAGES) * STAGE_HALVES) * 2u;

#pragma unroll
        for (int kk = 0; kk < BK; kk += 16) {
            uint32_t a[4][4], b[2][4];
#pragma unroll
            for (int tm = 0; tm < 4; tm++)
                ldsm_x4(a[tm][0], a[tm][1], a[tm][2], a[tm][3], st + aOff[tm] + kk * 2);
#pragma unroll
            for (int tp = 0; tp < 2; tp++)
                ldsm_x4(b[tp][0], b[tp][1], b[tp][2], b[tp][3], st + bOff[tp] + kk * 2);
#pragma unroll
            for (int tm = 0; tm < 4; tm++)
#pragma unroll
                for (int tn = 0; tn < 4; tn++)
                    mma_f16(d[tm][tn][0], d[tm][tn][1], d[tm][tn][2], d[tm][tn][3],
                            a[tm][0], a[tm][1], a[tm][2], a[tm][3],
                            b[tn >> 1][2 * (tn & 1)], b[tn >> 1][2 * (tn & 1) + 1]);
        }
    }

    // ---- Epilogue: d + bias -> gmem ----
#pragma unroll
    for (int tn = 0; tn < 4; tn++) {
        int col = n0 + Bn_base + tn * 8 + 2 * q;
        float2 bb = *reinterpret_cast<const float2*>(bias + col);
#pragma unroll
        for (int tm = 0; tm < 4; tm++) {
            int row0 = m0 + Am_base + tm * 16 + g;
            float2 v0 = make_float2(d[tm][tn][0] + bb.x, d[tm][tn][1] + bb.y);
            float2 v1 = make_float2(d[tm][tn][2] + bb.x, d[tm][tn][3] + bb.y);
            *reinterpret_cast<float2*>(out + (size_t)row0 * N_TOTAL + col) = v0;
            *reinterpret_cast<float2*>(out + (size_t)(row0 + 8) * N_TOTAL + col) = v1;
        }
    }
}

// ============================================================================
// Host launch
// ============================================================================
extern "C" void kernel_launch(void* const* d_in, const int* in_sizes, int n_in,
                              void* d_out, int out_size) {
    const float* x    = (const float*)d_in[0];  // [4,2048,4096]
    const float* W    = (const float*)d_in[1];  // [4096,4096] (out,in)
    const float* bias = (const float*)d_in[2];  // [4096]
    const float* A    = (const float*)d_in[3];  // [4096,32]
    const float* B    = (const float*)d_in[4];  // [32,4096]
    float* y          = (float*)d_out;          // [4,2048,4096]

    void* xh_ptr = nullptr;
    void* wh_ptr = nullptr;
    cudaGetSymbolAddress(&xh_ptr, g_Xh);
    cudaGetSymbolAddress(&wh_ptr, g_Wh);

    // 1) fused prep: weff blocks first (overlap FMA-bound weff with DRAM-bound conversion)
    prep_kernel<<<WEFF_BLOCKS + CONV_BLOCKS, 256>>>(x, W, A, B);
    // 2) main GEMM + bias epilogue
    cudaFuncSetAttribute((const void*)gemm_kernel,
                         cudaFuncAttributeMaxDynamicSharedMemorySize, SMEM_BYTES);
    gemm_kernel<<<(M_TOTAL / BM) * (N_TOTAL / BN), 256, SMEM_BYTES>>>(
        (const __half*)xh_ptr, (const __half*)wh_ptr, bias, y);
}